// round 1
// baseline (speedup 1.0000x reference)
#include <cuda_runtime.h>

// RSNN forward:
//   syn_t = (syn + x_t@w_in^T + z_{t-1}@w_rec^T) * AS
//   z_t   = (mem_{t-1} > 1)
//   mem_t = ((1 - z_t)*mem_{t-1} + syn_t) * AN
//   out_t = (out_{t-1} + z_t@w_out^T) * AS
// Outputs: out_hist [B,T,20] then spk_hist [B,T,1024], concatenated fp32.

#define T_STEPS 250
#define BATCH   256
#define IN_F    700
#define HID     1024
#define OUT_F   20
#define M_TOTAL (T_STEPS * BATCH)   // 64000

#define ALPHA_S 0.9048374180359595f   // exp(-0.1)
#define ALPHA_N 0.9753099120283326f   // exp(-0.025)

// Scratch (device globals are the allowed scratch mechanism)
__device__ float g_inp[(size_t)M_TOTAL * HID];   // 262 MB: x @ w_in^T, [t*B+b, h]
__device__ float g_wrecT[(size_t)HID * HID];     // 4 MB: w_rec transposed [j][h]

// ---------------------------------------------------------------------------
// Kernel 0: transpose w_rec -> g_wrecT so the spike gather is row-coalesced
// ---------------------------------------------------------------------------
__global__ void transpose_wrec(const float* __restrict__ w) {
    __shared__ float tile[32][33];
    int x0 = blockIdx.x * 32;
    int y0 = blockIdx.y * 32;
    int tx = threadIdx.x, ty = threadIdx.y;
#pragma unroll
    for (int i = 0; i < 32; i += 8)
        tile[ty + i][tx] = w[(size_t)(y0 + ty + i) * HID + (x0 + tx)];
    __syncthreads();
#pragma unroll
    for (int i = 0; i < 32; i += 8)
        g_wrecT[(size_t)(x0 + ty + i) * HID + (y0 + tx)] = tile[tx][ty + i];
}

// ---------------------------------------------------------------------------
// Kernel 1: g_inp[m, h] = sum_k X[m, k] * W[h, k]   (M=64000, N=1024, K=700)
// Classic 128x128 tile, BK=16, 256 threads, 8x8 per-thread microtile, fp32.
// ---------------------------------------------------------------------------
#define BM 128
#define BN 128
#define BK 16

__global__ void __launch_bounds__(256) gemm_in(const float* __restrict__ X,
                                               const float* __restrict__ W) {
    __shared__ float As[BK][BM];
    __shared__ float Bs[BK][BN];

    int bm = blockIdx.x * BM;
    int bn = blockIdx.y * BN;
    int tid = threadIdx.x;
    int tx = tid & 15;          // n-tile coord (0..15)
    int ty = tid >> 4;          // m-tile coord (0..15)
    int lr = tid >> 1;          // load row 0..127
    int lk = (tid & 1) * 8;     // load k offset 0 or 8

    float acc[8][8];
#pragma unroll
    for (int i = 0; i < 8; i++)
#pragma unroll
        for (int j = 0; j < 8; j++) acc[i][j] = 0.f;

    const float* Arow = X + (size_t)(bm + lr) * IN_F;
    const float* Brow = W + (size_t)(bn + lr) * IN_F;

    for (int k0 = 0; k0 < IN_F; k0 += BK) {
        if (k0 + BK <= IN_F) {
            // rows are 16B aligned: 700*4 = 2800 = 16*175; k0+lk multiple of 8
            float4 a0 = *(const float4*)(Arow + k0 + lk);
            float4 a1 = *(const float4*)(Arow + k0 + lk + 4);
            float4 b0 = *(const float4*)(Brow + k0 + lk);
            float4 b1 = *(const float4*)(Brow + k0 + lk + 4);
            As[lk + 0][lr] = a0.x; As[lk + 1][lr] = a0.y;
            As[lk + 2][lr] = a0.z; As[lk + 3][lr] = a0.w;
            As[lk + 4][lr] = a1.x; As[lk + 5][lr] = a1.y;
            As[lk + 6][lr] = a1.z; As[lk + 7][lr] = a1.w;
            Bs[lk + 0][lr] = b0.x; Bs[lk + 1][lr] = b0.y;
            Bs[lk + 2][lr] = b0.z; Bs[lk + 3][lr] = b0.w;
            Bs[lk + 4][lr] = b1.x; Bs[lk + 5][lr] = b1.y;
            Bs[lk + 6][lr] = b1.z; Bs[lk + 7][lr] = b1.w;
        } else {
#pragma unroll
            for (int i = 0; i < 8; i++) {
                int k = k0 + lk + i;
                As[lk + i][lr] = (k < IN_F) ? Arow[k] : 0.f;
                Bs[lk + i][lr] = (k < IN_F) ? Brow[k] : 0.f;
            }
        }
        __syncthreads();
#pragma unroll
        for (int k = 0; k < BK; k++) {
            float4 a0 = *(const float4*)&As[k][ty * 8];
            float4 a1 = *(const float4*)&As[k][ty * 8 + 4];
            float4 b0 = *(const float4*)&Bs[k][tx * 8];
            float4 b1 = *(const float4*)&Bs[k][tx * 8 + 4];
            float a[8] = {a0.x, a0.y, a0.z, a0.w, a1.x, a1.y, a1.z, a1.w};
            float b[8] = {b0.x, b0.y, b0.z, b0.w, b1.x, b1.y, b1.z, b1.w};
#pragma unroll
            for (int i = 0; i < 8; i++)
#pragma unroll
                for (int j = 0; j < 8; j++) acc[i][j] += a[i] * b[j];
        }
        __syncthreads();
    }

#pragma unroll
    for (int i = 0; i < 8; i++) {
        float* Crow = g_inp + (size_t)(bm + ty * 8 + i) * HID + bn + tx * 8;
        *(float4*)Crow       = make_float4(acc[i][0], acc[i][1], acc[i][2], acc[i][3]);
        *(float4*)(Crow + 4) = make_float4(acc[i][4], acc[i][5], acc[i][6], acc[i][7]);
    }
}

// ---------------------------------------------------------------------------
// Kernel 2: persistent recurrent scan. One CTA per batch element; thread h
// owns neuron h (syn, mem in registers). Spike set in shared, rebuilt per
// step via deterministic ballot/prefix-scan (no atomics -> reproducible).
// ---------------------------------------------------------------------------
__global__ void __launch_bounds__(1024, 2) rsnn_kernel(
    const float* __restrict__ w_out,   // [20,1024]
    float* __restrict__ out_hist,      // [B,T,20]
    float* __restrict__ spk_hist)      // [B,T,1024]
{
    int b = blockIdx.x;
    int h = threadIdx.x;
    int lane = h & 31;
    int warp = h >> 5;

    __shared__ int   s_list[2][HID];
    __shared__ int   s_cnt[2];
    __shared__ int   s_wcnt[32];
    __shared__ int   s_woff[32];
    __shared__ float s_out[OUT_F];

    if (h < 2) s_cnt[h] = 0;
    if (h < OUT_F) s_out[h] = 0.f;

    float syn = 0.f, mem = 0.f;
    const float* inp_b = g_inp + (size_t)b * HID;           // stride B*HID per t
    float* spk_b = spk_hist + (size_t)b * T_STEPS * HID;
    float* out_b = out_hist + (size_t)b * T_STEPS * OUT_F;
    const float* wout_row = w_out + (size_t)warp * HID;     // used only if warp<20

    __syncthreads();

    for (int t = 0; t < T_STEPS; t++) {
        int p = t & 1, q = p ^ 1;

        // issue input load early (overlaps the gather)
        float inpv = inp_b[(size_t)t * (BATCH * HID) + h];

        // sparse recurrent drive: sum of w_recT rows for previous-step spikes
        int s = s_cnt[p];
        const int* lst = s_list[p];
        float r = 0.f;
        int i = 0;
        for (; i + 4 <= s; i += 4) {
            int j0 = lst[i], j1 = lst[i + 1], j2 = lst[i + 2], j3 = lst[i + 3];
            float v0 = g_wrecT[(size_t)j0 * HID + h];
            float v1 = g_wrecT[(size_t)j1 * HID + h];
            float v2 = g_wrecT[(size_t)j2 * HID + h];
            float v3 = g_wrecT[(size_t)j3 * HID + h];
            r += v0; r += v1; r += v2; r += v3;
        }
        for (; i < s; i++) r += g_wrecT[(size_t)lst[i] * HID + h];

        syn = (syn + inpv + r) * ALPHA_S;
        bool z = mem > 1.0f;
        mem = (z ? syn : (mem + syn)) * ALPHA_N;
        spk_b[(size_t)t * HID + h] = z ? 1.0f : 0.0f;

        // deterministic compaction of spike indices into s_list[q]
        unsigned bal = __ballot_sync(0xffffffffu, z);
        if (lane == 0) s_wcnt[warp] = __popc(bal);
        __syncthreads();
        if (warp == 0) {
            int v = s_wcnt[lane];
#pragma unroll
            for (int off = 1; off < 32; off <<= 1) {
                int n = __shfl_up_sync(0xffffffffu, v, off);
                if (lane >= off) v += n;
            }
            s_woff[lane] = v;                 // inclusive scan
            if (lane == 31) s_cnt[q] = v;     // total
        }
        __syncthreads();
        if (z) {
            int base = (warp == 0) ? 0 : s_woff[warp - 1];
            int pos = base + __popc(bal & ((1u << lane) - 1u));
            s_list[q][pos] = h;
        }
        __syncthreads();

        // readout: warps 0..19 each reduce w_out[o, spikes]
        if (warp < OUT_F) {
            int cs = s_cnt[q];
            float sum = 0.f;
            for (int k = lane; k < cs; k += 32)
                sum += wout_row[s_list[q][k]];
#pragma unroll
            for (int off = 16; off; off >>= 1)
                sum += __shfl_down_sync(0xffffffffu, sum, off);
            if (lane == 0) {
                float ov = (s_out[warp] + sum) * ALPHA_S;
                s_out[warp] = ov;
                out_b[(size_t)t * OUT_F + warp] = ov;
            }
        }
        __syncthreads();
    }
}

// ---------------------------------------------------------------------------
extern "C" void kernel_launch(void* const* d_in, const int* in_sizes, int n_in,
                              void* d_out, int out_size) {
    const float* x     = (const float*)d_in[0];  // [T,B,IN]
    const float* w_in  = (const float*)d_in[1];  // [HID,IN]
    const float* w_rec = (const float*)d_in[2];  // [HID,HID]
    const float* w_out = (const float*)d_in[3];  // [OUT,HID]

    float* out_hist = (float*)d_out;                                   // [B,T,20]
    float* spk_hist = out_hist + (size_t)BATCH * T_STEPS * OUT_F;      // [B,T,1024]

    transpose_wrec<<<dim3(HID / 32, HID / 32), dim3(32, 8)>>>(w_rec);
    gemm_in<<<dim3(M_TOTAL / BM, HID / BN), 256>>>(x, w_in);
    rsnn_kernel<<<BATCH, 1024>>>(w_out, out_hist, spk_hist);
}

// round 8
// speedup vs baseline: 1.0170x; 1.0170x over previous
#include <cuda_runtime.h>
#include <cstdint>

// ===========================================================================
// RSNN forward (proven-numerics pipeline, R1 arithmetic, faster schedule).
// Phase 1: inp = x @ w_in^T as fp32 SIMT GEMM — BITWISE-identical FFMA order
//   to the R1 kernel that passed (k-ascending per output), but with
//   register-staged double-buffered smem (1 barrier/tile, LDG overlapped)
//   and N-fastest grid order (A tiles L2-resident across their 8 users).
// Phase 2: per-batch persistent recurrent scan with sparse spike gather
//   (R1 logic; gather unrolled 8 with order-preserving adds).
// ===========================================================================

#define T_STEPS 250
#define BATCH   256
#define IN_F    700
#define HID     1024
#define OUT_F   20
#define M_TOTAL (T_STEPS * BATCH)   // 64000

#define ALPHA_S 0.9048374180359595f
#define ALPHA_N 0.9753099120283326f

#define BM 128
#define BN 128
#define BK 16
#define NTILE 44                    // ceil(700/16) -> 44 tiles (last guarded)

// ---- scratch (device globals) ----
__device__ float g_inp[(size_t)M_TOTAL * HID];   // 262 MB
__device__ float g_wrecT[(size_t)HID * HID];     // 4 MB

// ---------------------------------------------------------------------------
// transpose w_rec -> g_wrecT (row-coalesced spike gather)
// ---------------------------------------------------------------------------
__global__ void transpose_wrec(const float* __restrict__ w) {
    __shared__ float tile[32][33];
    int x0 = blockIdx.x * 32, y0 = blockIdx.y * 32;
    int tx = threadIdx.x, ty = threadIdx.y;
#pragma unroll
    for (int i = 0; i < 32; i += 8)
        tile[ty + i][tx] = w[(size_t)(y0 + ty + i) * HID + (x0 + tx)];
    __syncthreads();
#pragma unroll
    for (int i = 0; i < 32; i += 8)
        g_wrecT[(size_t)(x0 + ty + i) * HID + (y0 + tx)] = tile[tx][ty + i];
}

// ---------------------------------------------------------------------------
// fp32 GEMM, R1-identical arithmetic, double-buffered smem.
// grid: (x = N tiles = 8, y = M tiles = 500)  -> A tile reused via L2.
// ---------------------------------------------------------------------------
__global__ void __launch_bounds__(256) gemm_in(const float* __restrict__ X,
                                               const float* __restrict__ W) {
    __shared__ float As[2][BK][BM];
    __shared__ float Bs[2][BK][BN];

    int tid = threadIdx.x;
    int tx = tid & 15;          // n microtile coord
    int ty = tid >> 4;          // m microtile coord
    int lr = tid >> 1;          // load row 0..127
    int lk = (tid & 1) * 8;     // load k offset 0 or 8

    size_t bm = (size_t)blockIdx.y * BM;
    size_t bn = (size_t)blockIdx.x * BN;

    float acc[8][8];
#pragma unroll
    for (int i = 0; i < 8; i++)
#pragma unroll
        for (int j = 0; j < 8; j++) acc[i][j] = 0.f;

    const float* Arow = X + (bm + lr) * IN_F;
    const float* Brow = W + (bn + lr) * IN_F;

    // ---- prologue: tile 0 (full, vectorized) into stage 0 ----
    {
        float4 a0 = *(const float4*)(Arow + lk);
        float4 a1 = *(const float4*)(Arow + lk + 4);
        float4 b0 = *(const float4*)(Brow + lk);
        float4 b1 = *(const float4*)(Brow + lk + 4);
        As[0][lk + 0][lr] = a0.x; As[0][lk + 1][lr] = a0.y;
        As[0][lk + 2][lr] = a0.z; As[0][lk + 3][lr] = a0.w;
        As[0][lk + 4][lr] = a1.x; As[0][lk + 5][lr] = a1.y;
        As[0][lk + 6][lr] = a1.z; As[0][lk + 7][lr] = a1.w;
        Bs[0][lk + 0][lr] = b0.x; Bs[0][lk + 1][lr] = b0.y;
        Bs[0][lk + 2][lr] = b0.z; Bs[0][lk + 3][lr] = b0.w;
        Bs[0][lk + 4][lr] = b1.x; Bs[0][lk + 5][lr] = b1.y;
        Bs[0][lk + 6][lr] = b1.z; Bs[0][lk + 7][lr] = b1.w;
    }

    for (int t = 0; t < NTILE; t++) {
        int st = t & 1;
        bool haveNext = (t + 1) < NTILE;

        // stage next tile's data into registers (overlaps with compute)
        float sa[8], sb[8];
        if (haveNext) {
            int k0 = (t + 1) * BK;
            if (t + 1 < NTILE - 1) {
                float4 a0 = *(const float4*)(Arow + k0 + lk);
                float4 a1 = *(const float4*)(Arow + k0 + lk + 4);
                float4 b0 = *(const float4*)(Brow + k0 + lk);
                float4 b1 = *(const float4*)(Brow + k0 + lk + 4);
                sa[0] = a0.x; sa[1] = a0.y; sa[2] = a0.z; sa[3] = a0.w;
                sa[4] = a1.x; sa[5] = a1.y; sa[6] = a1.z; sa[7] = a1.w;
                sb[0] = b0.x; sb[1] = b0.y; sb[2] = b0.z; sb[3] = b0.w;
                sb[4] = b1.x; sb[5] = b1.y; sb[6] = b1.z; sb[7] = b1.w;
            } else {
#pragma unroll
                for (int i = 0; i < 8; i++) {
                    int k = k0 + lk + i;
                    sa[i] = (k < IN_F) ? Arow[k] : 0.f;
                    sb[i] = (k < IN_F) ? Brow[k] : 0.f;
                }
            }
        }

        __syncthreads();   // stage st fully written (prologue or prev iter)

        // ---- compute on stage st: R1-identical inner loop ----
#pragma unroll
        for (int k = 0; k < BK; k++) {
            float4 a0 = *(const float4*)&As[st][k][ty * 8];
            float4 a1 = *(const float4*)&As[st][k][ty * 8 + 4];
            float4 b0 = *(const float4*)&Bs[st][k][tx * 8];
            float4 b1 = *(const float4*)&Bs[st][k][tx * 8 + 4];
            float a[8] = {a0.x, a0.y, a0.z, a0.w, a1.x, a1.y, a1.z, a1.w};
            float b[8] = {b0.x, b0.y, b0.z, b0.w, b1.x, b1.y, b1.z, b1.w};
#pragma unroll
            for (int i = 0; i < 8; i++)
#pragma unroll
                for (int j = 0; j < 8; j++) acc[i][j] += a[i] * b[j];
        }

        // ---- store staged regs into the other buffer ----
        if (haveNext) {
            int ns = st ^ 1;
#pragma unroll
            for (int i = 0; i < 8; i++) {
                As[ns][lk + i][lr] = sa[i];
                Bs[ns][lk + i][lr] = sb[i];
            }
        }
    }

#pragma unroll
    for (int i = 0; i < 8; i++) {
        float* Crow = g_inp + (bm + ty * 8 + i) * HID + bn + tx * 8;
        *(float4*)Crow       = make_float4(acc[i][0], acc[i][1], acc[i][2], acc[i][3]);
        *(float4*)(Crow + 4) = make_float4(acc[i][4], acc[i][5], acc[i][6], acc[i][7]);
    }
}

// ---------------------------------------------------------------------------
// persistent recurrent scan (R1 logic; order-preserving 8-wide gather)
// ---------------------------------------------------------------------------
__global__ void __launch_bounds__(1024, 2) rsnn_kernel(
    const float* __restrict__ w_out,
    float* __restrict__ out_hist,
    float* __restrict__ spk_hist)
{
    int b = blockIdx.x;
    int h = threadIdx.x;
    int lane = h & 31;
    int warp = h >> 5;

    __shared__ int   s_list[2][HID];
    __shared__ int   s_cnt[2];
    __shared__ int   s_wcnt[32];
    __shared__ int   s_woff[32];
    __shared__ float s_out[OUT_F];

    if (h < 2) s_cnt[h] = 0;
    if (h < OUT_F) s_out[h] = 0.f;

    float syn = 0.f, mem = 0.f;
    const float* inp_b = g_inp + (size_t)b * HID;
    float* spk_b = spk_hist + (size_t)b * T_STEPS * HID;
    float* out_b = out_hist + (size_t)b * T_STEPS * OUT_F;
    const float* wout_row = w_out + (size_t)warp * HID;

    __syncthreads();

    for (int t = 0; t < T_STEPS; t++) {
        int p = t & 1, q = p ^ 1;
        float inpv = inp_b[(size_t)t * (BATCH * HID) + h];

        int s = s_cnt[p];
        const int* lst = s_list[p];
        float r = 0.f;
        int i = 0;
        for (; i + 8 <= s; i += 8) {
            float v0 = g_wrecT[(size_t)lst[i + 0] * HID + h];
            float v1 = g_wrecT[(size_t)lst[i + 1] * HID + h];
            float v2 = g_wrecT[(size_t)lst[i + 2] * HID + h];
            float v3 = g_wrecT[(size_t)lst[i + 3] * HID + h];
            float v4 = g_wrecT[(size_t)lst[i + 4] * HID + h];
            float v5 = g_wrecT[(size_t)lst[i + 5] * HID + h];
            float v6 = g_wrecT[(size_t)lst[i + 6] * HID + h];
            float v7 = g_wrecT[(size_t)lst[i + 7] * HID + h];
            r += v0; r += v1; r += v2; r += v3;
            r += v4; r += v5; r += v6; r += v7;
        }
        for (; i < s; i++) r += g_wrecT[(size_t)lst[i] * HID + h];

        syn = (syn + inpv + r) * ALPHA_S;
        bool z = mem > 1.0f;
        mem = (z ? syn : (mem + syn)) * ALPHA_N;
        spk_b[(size_t)t * HID + h] = z ? 1.0f : 0.0f;

        unsigned bal = __ballot_sync(0xffffffffu, z);
        if (lane == 0) s_wcnt[warp] = __popc(bal);
        __syncthreads();
        if (warp == 0) {
            int v = s_wcnt[lane];
#pragma unroll
            for (int off = 1; off < 32; off <<= 1) {
                int n = __shfl_up_sync(0xffffffffu, v, off);
                if (lane >= off) v += n;
            }
            s_woff[lane] = v;
            if (lane == 31) s_cnt[q] = v;
        }
        __syncthreads();
        if (z) {
            int base = (warp == 0) ? 0 : s_woff[warp - 1];
            int pos = base + __popc(bal & ((1u << lane) - 1u));
            s_list[q][pos] = h;
        }
        __syncthreads();

        if (warp < OUT_F) {
            int cs = s_cnt[q];
            float sum = 0.f;
            for (int k = lane; k < cs; k += 32)
                sum += wout_row[s_list[q][k]];
#pragma unroll
            for (int off = 16; off; off >>= 1)
                sum += __shfl_down_sync(0xffffffffu, sum, off);
            if (lane == 0) {
                float ov = (s_out[warp] + sum) * ALPHA_S;
                s_out[warp] = ov;
                out_b[(size_t)t * OUT_F + warp] = ov;
            }
        }
        __syncthreads();
    }
}

// ---------------------------------------------------------------------------
extern "C" void kernel_launch(void* const* d_in, const int* in_sizes, int n_in,
                              void* d_out, int out_size) {
    const float* x     = (const float*)d_in[0];
    const float* w_in  = (const float*)d_in[1];
    const float* w_rec = (const float*)d_in[2];
    const float* w_out = (const float*)d_in[3];

    float* out_hist = (float*)d_out;
    float* spk_hist = out_hist + (size_t)BATCH * T_STEPS * OUT_F;

    transpose_wrec<<<dim3(HID / 32, HID / 32), dim3(32, 8)>>>(w_rec);
    gemm_in<<<dim3(HID / BN, M_TOTAL / BM), 256>>>(x, w_in);
    rsnn_kernel<<<BATCH, 1024>>>(w_out, out_hist, spk_hist);
}